// round 15
// baseline (speedup 1.0000x reference)
#include <cuda_runtime.h>
#include <cuda_fp16.h>
#include <cstdint>

// Problem constants (fixed by the dataset)
constexpr int NN   = 20000;     // nodes
constexpr int EE   = 320000;    // edges
constexpr int S    = 2;         // feature axis
constexpr int IN_F = 128;       // input features
constexpr int H    = 246;       // hidden
constexpr int HP   = 248;       // padded hidden (halves per row, 16B-friendly)
constexpr int MROWS = NN * S;   // 40000 GEMM rows
constexpr int NBLK = (NN + 255) / 256;  // 79
constexpr int NODE_U4 = (S * HP) / 8;   // 62 uint4 lanes per node (496 halves)

// ---------------- static device scratch (no allocations allowed) -------------
// zero-initialized at module load; g_hbuf pad columns are never written -> stay 0
__device__ __align__(128) float  g_buf1[MROWS * HP];   // agg output (fp32, lda-padded)
__device__ __align__(128) __half g_hbuf[MROWS * HP];   // GEMM output (fp16, padded)
__device__ float g_norm_out[NN];
__device__ float g_norm_in[NN];
__device__ int   g_outdeg[NN];
__device__ int   g_indeg[NN];
__device__ int   g_rowptr[NN + 1];
__device__ int   g_cursor[NN];
__device__ int   g_esrc[EE];
__device__ unsigned long long g_scanstate[NBLK];

// ---------------- graph preprocessing ---------------------------------------
__global__ void k_deg(const int* __restrict__ src, const int* __restrict__ dst) {
    int i = blockIdx.x * blockDim.x + threadIdx.x;
    if (i < NBLK) g_scanstate[i] = 0ull;   // reset lookback state for k_scan1
    if (i < EE) {
        atomicAdd(&g_outdeg[src[i]], 1);
        atomicAdd(&g_indeg[dst[i]], 1);
    }
}

// single-kernel scan: local scan + warp-parallel lookback over block aggregates
// (NBLK=79 blocks all co-resident on 148 SMs -> spin-wait is deadlock-free)
__global__ void k_scan1() {   // NBLK blocks x 256
    __shared__ int sd[256];
    __shared__ int s_base;
    int t = threadIdx.x, b = blockIdx.x;
    int i = b * 256 + t;
    int deg = (i < NN) ? g_indeg[i] : 0;
    int v = deg;
    sd[t] = v; __syncthreads();
    #pragma unroll
    for (int off = 1; off < 256; off <<= 1) {
        int tmp = (t >= off) ? sd[t - off] : 0;
        __syncthreads();
        v += tmp; sd[t] = v;
        __syncthreads();
    }
    int total = sd[255];
    if (t == 0)   // publish this block's aggregate (flag in high word)
        atomicExch(&g_scanstate[b], (1ull << 32) | (unsigned)total);
    if (t < 32) { // warp 0: sum all predecessor aggregates
        long long acc = 0;
        for (int j = b - 1 - t; j >= 0; j -= 32) {
            unsigned long long s;
            do { s = atomicAdd(&g_scanstate[j], 0ull); } while ((s >> 32) == 0);
            acc += (int)(s & 0xffffffffull);
        }
        #pragma unroll
        for (int off = 16; off; off >>= 1)
            acc += __shfl_down_sync(0xffffffffu, acc, off);
        if (t == 0) s_base = (int)acc;
    }
    __syncthreads();
    int base = s_base;
    if (i < NN) {
        g_rowptr[i + 1] = base + v;
        g_cursor[i]     = base + v - deg;
        g_norm_in[i]    = rsqrtf((float)max(deg, 1));
        g_norm_out[i]   = rsqrtf((float)max(g_outdeg[i], 1));
    }
    if (i == 0) g_rowptr[0] = 0;
}

__global__ void k_scatter(const int* __restrict__ src, const int* __restrict__ dst) {
    int i = blockIdx.x * blockDim.x + threadIdx.x;
    if (i < EE) {
        int p = atomicAdd(&g_cursor[dst[i]], 1);
        g_esrc[p] = src[i];
    }
}

// ---------------- layer-0 aggregation fused with norm_out pre-scale ----------
// reads fp32 features directly; writes buf1 [MROWS][128] (lda=128)
__global__ void k_agg0(const float* __restrict__ feat) {
    constexpr int SF4 = S * IN_F / 4;   // 64
    int n = blockIdx.x;
    int t = threadIdx.x;
    int beg = g_rowptr[n];
    int end = g_rowptr[n + 1];
    const float4* base = reinterpret_cast<const float4*>(feat);
    float4 a = make_float4(0.f, 0.f, 0.f, 0.f);
    float4 b = make_float4(0.f, 0.f, 0.f, 0.f);
    int e = beg;
    for (; e + 4 <= end; e += 4) {
        int s0 = g_esrc[e],     s1 = g_esrc[e + 1];
        int s2 = g_esrc[e + 2], s3 = g_esrc[e + 3];
        float w0 = g_norm_out[s0], w1 = g_norm_out[s1];
        float w2 = g_norm_out[s2], w3 = g_norm_out[s3];
        float4 v0 = base[(size_t)s0 * SF4 + t];
        float4 v1 = base[(size_t)s1 * SF4 + t];
        float4 v2 = base[(size_t)s2 * SF4 + t];
        float4 v3 = base[(size_t)s3 * SF4 + t];
        a.x += v0.x * w0 + v1.x * w1;  b.x += v2.x * w2 + v3.x * w3;
        a.y += v0.y * w0 + v1.y * w1;  b.y += v2.y * w2 + v3.y * w3;
        a.z += v0.z * w0 + v1.z * w1;  b.z += v2.z * w2 + v3.z * w3;
        a.w += v0.w * w0 + v1.w * w1;  b.w += v2.w * w2 + v3.w * w3;
    }
    for (; e < end; e++) {
        int s = g_esrc[e];
        float w = g_norm_out[s];
        float4 v = base[(size_t)s * SF4 + t];
        a.x += v.x * w; a.y += v.y * w; a.z += v.z * w; a.w += v.w * w;
    }
    float ni = g_norm_in[n];
    reinterpret_cast<float4*>(g_buf1)[(size_t)n * SF4 + t] = make_float4(
        (a.x + b.x) * ni, (a.y + b.y) * ni, (a.z + b.z) * ni, (a.w + b.w) * ni);
}

// ---------------- layers 1/2 aggregation: fp16 gather -> fp32 accumulate -----
// reads g_hbuf [node][496 halves incl pads], writes g_buf1 [node][496 floats]
__global__ void k_aggh() {
    int n = blockIdx.x;
    int t = threadIdx.x;           // 0..63
    if (t >= NODE_U4) return;      // 62 active lanes
    int beg = g_rowptr[n];
    int end = g_rowptr[n + 1];
    const uint4* base = reinterpret_cast<const uint4*>(g_hbuf);
    float a[8], b[8];
    #pragma unroll
    for (int q = 0; q < 8; q++) { a[q] = 0.f; b[q] = 0.f; }

    auto addu4 = [](float* acc, uint4 u) {
        const __half2* h2 = reinterpret_cast<const __half2*>(&u);
        #pragma unroll
        for (int q = 0; q < 4; q++) {
            float2 f = __half22float2(h2[q]);
            acc[2 * q]     += f.x;
            acc[2 * q + 1] += f.y;
        }
    };

    int e = beg;
    for (; e + 4 <= end; e += 4) {
        int s0 = g_esrc[e],     s1 = g_esrc[e + 1];
        int s2 = g_esrc[e + 2], s3 = g_esrc[e + 3];
        uint4 u0 = base[(size_t)s0 * NODE_U4 + t];
        uint4 u1 = base[(size_t)s1 * NODE_U4 + t];
        uint4 u2 = base[(size_t)s2 * NODE_U4 + t];
        uint4 u3 = base[(size_t)s3 * NODE_U4 + t];
        addu4(a, u0); addu4(b, u1); addu4(a, u2); addu4(b, u3);
    }
    for (; e < end; e++) {
        uint4 u = base[(size_t)g_esrc[e] * NODE_U4 + t];
        addu4(a, u);
    }
    float ni = g_norm_in[n];
    float4 o0, o1;
    o0.x = (a[0] + b[0]) * ni; o0.y = (a[1] + b[1]) * ni;
    o0.z = (a[2] + b[2]) * ni; o0.w = (a[3] + b[3]) * ni;
    o1.x = (a[4] + b[4]) * ni; o1.y = (a[5] + b[5]) * ni;
    o1.z = (a[6] + b[6]) * ni; o1.w = (a[7] + b[7]) * ni;
    float4* out = reinterpret_cast<float4*>(g_buf1) + (size_t)n * (NODE_U4 * 2);
    out[2 * t]     = o0;
    out[2 * t + 1] = o1;
}

// ---------------- tf32 tensor-core GEMM (double-buffered, reg-prefetched) ----
// C(fp16) = relu(buf1[M,K,lda] @ W[K,246] + b) * (use_scale ? norm_out : 1)
__device__ __forceinline__ uint32_t to_tf32(float f) {
    uint32_t u;
    asm("cvt.rna.tf32.f32 %0, %1;" : "=r"(u) : "f"(f));
    return u;
}

#define MMA_TF32(c, a, b)                                              \
    asm volatile(                                                      \
        "mma.sync.aligned.m16n8k8.row.col.f32.tf32.tf32.f32 "          \
        "{%0,%1,%2,%3}, {%4,%5,%6,%7}, {%8,%9}, {%0,%1,%2,%3};"        \
        : "+f"((c)[0]), "+f"((c)[1]), "+f"((c)[2]), "+f"((c)[3])       \
        : "r"((a)[0]), "r"((a)[1]), "r"((a)[2]), "r"((a)[3]),          \
          "r"((b)[0]), "r"((b)[1]))

constexpr int BM = 128, BN = 128, BK = 16;

__global__ void __launch_bounds__(256)
k_gemm(int K, int lda, const float* __restrict__ W, const float* __restrict__ bias,
       int use_scale) {
    __shared__ uint32_t As[2][BK][BM + 8];   // [buf][k][m]
    __shared__ uint32_t Bs[2][BK][BN + 8];   // [buf][k][n]

    int tid = threadIdx.x;
    int lane = tid & 31, warp = tid >> 5;
    int wm = (warp & 1) * 64;     // 2 warps along M
    int wn = (warp >> 1) * 32;    // 4 warps along N
    int row0 = blockIdx.y * BM;
    int col0 = blockIdx.x * BN;

    int f2c = tid & 7;        // A: k-pair 0..7
    int rb  = tid >> 3;       // A: row base 0..31
    int f2n = tid & 63;       // B: n-pair 0..63
    int rkb = tid >> 6;       // B: k base 0..3

    float2 aR[4], bR[4];

    auto load_tile = [&](int kt) {
        int k0 = kt * BK;
        #pragma unroll
        for (int it = 0; it < 4; it++) {
            int grow = row0 + rb + it * 32;
            int k = k0 + f2c * 2;
            aR[it] = make_float2(0.f, 0.f);
            if (grow < MROWS && k < K)
                aR[it] = *reinterpret_cast<const float2*>(&g_buf1[(size_t)grow * lda + k]);
        }
        #pragma unroll
        for (int it = 0; it < 4; it++) {
            int k = k0 + rkb + it * 4;
            int cc = col0 + f2n * 2;
            bR[it] = make_float2(0.f, 0.f);
            if (k < K && cc < H)
                bR[it] = *reinterpret_cast<const float2*>(&W[(size_t)k * H + cc]);
        }
    };
    auto store_tile = [&](int buf) {
        #pragma unroll
        for (int it = 0; it < 4; it++) {
            As[buf][f2c * 2][rb + it * 32]     = to_tf32(aR[it].x);
            As[buf][f2c * 2 + 1][rb + it * 32] = to_tf32(aR[it].y);
        }
        #pragma unroll
        for (int it = 0; it < 4; it++) {
            Bs[buf][rkb + it * 4][f2n * 2]     = to_tf32(bR[it].x);
            Bs[buf][rkb + it * 4][f2n * 2 + 1] = to_tf32(bR[it].y);
        }
    };

    float c[4][4][4];
    #pragma unroll
    for (int mi = 0; mi < 4; mi++)
        #pragma unroll
        for (int nj = 0; nj < 4; nj++)
            #pragma unroll
            for (int q = 0; q < 4; q++) c[mi][nj][q] = 0.f;

    int ktiles = (K + BK - 1) / BK;
    load_tile(0);
    store_tile(0);
    __syncthreads();

    for (int kt = 0; kt < ktiles; kt++) {
        int cur = kt & 1;
        bool more = (kt + 1) < ktiles;
        if (more) load_tile(kt + 1);          // LDGs fly during MMA below

        #pragma unroll
        for (int ks = 0; ks < BK; ks += 8) {
            uint32_t a[4][4], b[4][2];
            int kq = ks + (lane & 3);
            int mb = wm + (lane >> 2);
            #pragma unroll
            for (int mi = 0; mi < 4; mi++) {
                a[mi][0] = As[cur][kq][mb + mi * 16];
                a[mi][1] = As[cur][kq][mb + mi * 16 + 8];
                a[mi][2] = As[cur][kq + 4][mb + mi * 16];
                a[mi][3] = As[cur][kq + 4][mb + mi * 16 + 8];
            }
            int nb = wn + (lane >> 2);
            #pragma unroll
            for (int nj = 0; nj < 4; nj++) {
                b[nj][0] = Bs[cur][kq][nb + nj * 8];
                b[nj][1] = Bs[cur][kq + 4][nb + nj * 8];
            }
            #pragma unroll
            for (int mi = 0; mi < 4; mi++)
                #pragma unroll
                for (int nj = 0; nj < 4; nj++)
                    MMA_TF32(c[mi][nj], a[mi], b[nj]);
        }

        if (more) {
            store_tile(cur ^ 1);
            __syncthreads();
        }
    }

    // epilogue: bias + relu (+ optional norm_out pre-scale), fp16 half2 stores
    #pragma unroll
    for (int mi = 0; mi < 4; mi++) {
        int r  = row0 + wm + mi * 16 + (lane >> 2);
        int r2 = r + 8;
        float sc  = 1.f, sc2 = 1.f;
        if (use_scale) {
            if (r  < MROWS) sc  = g_norm_out[r >> 1];
            if (r2 < MROWS) sc2 = g_norm_out[r2 >> 1];
        }
        #pragma unroll
        for (int nj = 0; nj < 4; nj++) {
            int cc = col0 + wn + nj * 8 + (lane & 3) * 2;
            if (cc >= H) continue;           // H even -> pair never straddles
            float b0 = bias[cc];
            float b1 = bias[cc + 1];
            if (r < MROWS) {
                float v0 = fmaxf(c[mi][nj][0] + b0, 0.f) * sc;
                float v1 = fmaxf(c[mi][nj][1] + b1, 0.f) * sc;
                *reinterpret_cast<__half2*>(&g_hbuf[(size_t)r * HP + cc]) =
                    __floats2half2_rn(v0, v1);
            }
            if (r2 < MROWS) {
                float v2 = fmaxf(c[mi][nj][2] + b0, 0.f) * sc2;
                float v3 = fmaxf(c[mi][nj][3] + b1, 0.f) * sc2;
                *reinterpret_cast<__half2*>(&g_hbuf[(size_t)r2 * HP + cc]) =
                    __floats2half2_rn(v2, v3);
            }
        }
    }
}

// ---------------- final fc: out[n] = fc_b + mean_s(h[n,s,:]) @ fc_w ----------
__global__ void k_fc(const float* __restrict__ fcw, const float* __restrict__ fcb,
                     float* __restrict__ out) {
    int gwarp = (blockIdx.x * blockDim.x + threadIdx.x) >> 5;
    int lane = threadIdx.x & 31;
    if (gwarp >= NN) return;
    const __half2* p = reinterpret_cast<const __half2*>(g_hbuf + (size_t)gwarp * (S * HP));
    float acc = 0.f;
    for (int q = lane; q < S * HP / 2; q += 32) {   // 248 half2 per node
        int row = (q >= HP / 2) ? 1 : 0;
        int col = (q - row * (HP / 2)) * 2;
        if (col >= H) continue;                      // pad columns
        float2 f = __half22float2(p[q]);
        acc += f.x * fcw[col] + f.y * fcw[col + 1];
    }
    #pragma unroll
    for (int off = 16; off; off >>= 1)
        acc += __shfl_down_sync(0xffffffffu, acc, off);
    if (lane == 0) out[gwarp] = fcb[0] + acc * (1.0f / S);
}

// ---------------- launch -----------------------------------------------------
extern "C" void kernel_launch(void* const* d_in, const int* in_sizes, int n_in,
                              void* d_out, int out_size) {
    const float* feat = (const float*)d_in[0];
    const int*   src  = (const int*)d_in[1];
    const int*   dst  = (const int*)d_in[2];
    const float* W0   = (const float*)d_in[3];
    const float* b0   = (const float*)d_in[4];
    const float* W1   = (const float*)d_in[5];
    const float* b1   = (const float*)d_in[6];
    const float* W2   = (const float*)d_in[7];
    const float* b2   = (const float*)d_in[8];
    const float* fcw  = (const float*)d_in[9];
    const float* fcb  = (const float*)d_in[10];
    float* out = (float*)d_out;

    // zero degree arrays via async memset (graph-capturable)
    void* p_out; void* p_in;
    cudaGetSymbolAddress(&p_out, g_outdeg);
    cudaGetSymbolAddress(&p_in,  g_indeg);
    cudaMemsetAsync(p_out, 0, NN * sizeof(int), 0);
    cudaMemsetAsync(p_in,  0, NN * sizeof(int), 0);

    // graph build: deg (+scanstate reset) -> one-kernel scan -> scatter
    k_deg<<<(EE + 255) / 256, 256>>>(src, dst);
    k_scan1<<<NBLK, 256>>>();
    k_scatter<<<(EE + 255) / 256, 256>>>(src, dst);

    dim3 gg(2, (MROWS + BM - 1) / BM);

    // layer 0: fused prescale+aggregate (fp32) -> GEMM K=128, lda=128
    k_agg0<<<NN, S * IN_F / 4>>>(feat);
    k_gemm<<<gg, 256>>>(IN_F, IN_F, W0, b0, /*use_scale=*/1);

    // layer 1: fp16 gather-agg -> GEMM K=246, lda=248
    k_aggh<<<NN, 64>>>();
    k_gemm<<<gg, 256>>>(H, HP, W1, b1, /*use_scale=*/1);

    // layer 2 (no pre-scale; feeds fc)
    k_aggh<<<NN, 64>>>();
    k_gemm<<<gg, 256>>>(H, HP, W2, b2, /*use_scale=*/0);

    // readout
    k_fc<<<(NN * 32 + 255) / 256, 256>>>(fcw, fcb, out);
}

// round 16
// speedup vs baseline: 1.2839x; 1.2839x over previous
#include <cuda_runtime.h>
#include <cuda_fp16.h>
#include <cstdint>

// Problem constants (fixed by the dataset)
constexpr int NN   = 20000;     // nodes
constexpr int EE   = 320000;    // edges
constexpr int S    = 2;         // feature axis
constexpr int IN_F = 128;       // input features
constexpr int H    = 246;       // hidden
constexpr int HP   = 248;       // padded hidden (halves per row, 16B-friendly)
constexpr int MROWS = NN * S;   // 40000 GEMM rows
constexpr int NBLK = (NN + 255) / 256;  // 79
constexpr int NODE_U4 = (S * HP) / 8;   // 62 uint4 lanes per node (496 halves)
constexpr int WPN = 256;        // padded W columns (uint32/half2 units)

// ---------------- static device scratch (no allocations allowed) -------------
// zero-initialized at module load; pad regions are never written -> stay 0
__device__ __align__(128) __half   g_abuf0[MROWS * IN_F]; // layer-0 agg out (fp16)
__device__ __align__(128) __half   g_abuf [MROWS * HP];   // layer-1/2 agg out (fp16)
__device__ __align__(128) __half   g_hbuf [MROWS * HP];   // GEMM out (fp16)
__device__ __align__(128) uint32_t g_wp[3][128 * WPN];    // k-pair-packed fp16 weights
__device__ float g_norm_out[NN];
__device__ float g_norm_in[NN];
__device__ int   g_outdeg[NN];
__device__ int   g_indeg[NN];
__device__ int   g_rowptr[NN + 1];
__device__ int   g_cursor[NN];
__device__ int   g_esrc[EE];
__device__ unsigned long long g_scanstate[NBLK];

// ---------------- weight pre-conversion: fp32 [K][246] -> half2 [kp][256] ----
// g_wp[w][kp*WPN + c] = {W[2kp][c], W[2kp+1][c]}; pads (kp>=K/2, c>=246) stay 0
__global__ void k_convw(const float* __restrict__ W0, const float* __restrict__ W1,
                        const float* __restrict__ W2) {
    int w = blockIdx.y, kp = blockIdx.x, c = threadIdx.x;
    const float* W = (w == 0) ? W0 : (w == 1) ? W1 : W2;
    int K = (w == 0) ? IN_F : H;
    if (c >= H || 2 * kp + 1 >= K) return;
    __half2 h = __floats2half2_rn(W[(size_t)(2 * kp) * H + c],
                                  W[(size_t)(2 * kp + 1) * H + c]);
    g_wp[w][kp * WPN + c] = *reinterpret_cast<uint32_t*>(&h);
}

// ---------------- graph preprocessing ---------------------------------------
__global__ void k_deg(const int* __restrict__ src, const int* __restrict__ dst) {
    int i = blockIdx.x * blockDim.x + threadIdx.x;
    if (i < NBLK) g_scanstate[i] = 0ull;   // reset lookback state for k_scan1
    if (i < EE) {
        atomicAdd(&g_outdeg[src[i]], 1);
        atomicAdd(&g_indeg[dst[i]], 1);
    }
}

// single-kernel scan: local scan + warp-parallel lookback over block aggregates
__global__ void k_scan1() {   // NBLK blocks x 256
    __shared__ int sd[256];
    __shared__ int s_base;
    int t = threadIdx.x, b = blockIdx.x;
    int i = b * 256 + t;
    int deg = (i < NN) ? g_indeg[i] : 0;
    int v = deg;
    sd[t] = v; __syncthreads();
    #pragma unroll
    for (int off = 1; off < 256; off <<= 1) {
        int tmp = (t >= off) ? sd[t - off] : 0;
        __syncthreads();
        v += tmp; sd[t] = v;
        __syncthreads();
    }
    int total = sd[255];
    if (t == 0)
        atomicExch(&g_scanstate[b], (1ull << 32) | (unsigned)total);
    if (t < 32) {
        long long acc = 0;
        for (int j = b - 1 - t; j >= 0; j -= 32) {
            unsigned long long s;
            do { s = atomicAdd(&g_scanstate[j], 0ull); } while ((s >> 32) == 0);
            acc += (int)(s & 0xffffffffull);
        }
        #pragma unroll
        for (int off = 16; off; off >>= 1)
            acc += __shfl_down_sync(0xffffffffu, acc, off);
        if (t == 0) s_base = (int)acc;
    }
    __syncthreads();
    int base = s_base;
    if (i < NN) {
        g_rowptr[i + 1] = base + v;
        g_cursor[i]     = base + v - deg;
        g_norm_in[i]    = rsqrtf((float)max(deg, 1));
        g_norm_out[i]   = rsqrtf((float)max(g_outdeg[i], 1));
    }
    if (i == 0) g_rowptr[0] = 0;
}

__global__ void k_scatter(const int* __restrict__ src, const int* __restrict__ dst) {
    int i = blockIdx.x * blockDim.x + threadIdx.x;
    if (i < EE) {
        int p = atomicAdd(&g_cursor[dst[i]], 1);
        g_esrc[p] = src[i];
    }
}

// ---------------- layer-0 aggregation fused with norm_out pre-scale ----------
// reads fp32 features; writes fp16 g_abuf0 [MROWS][128]
__global__ void k_agg0(const float* __restrict__ feat) {
    constexpr int SF4 = S * IN_F / 4;   // 64
    int n = blockIdx.x;
    int t = threadIdx.x;                // 0..63, covers floats [4t..4t+3]
    int beg = g_rowptr[n];
    int end = g_rowptr[n + 1];
    const float4* base = reinterpret_cast<const float4*>(feat);
    float4 a = make_float4(0.f, 0.f, 0.f, 0.f);
    float4 b = make_float4(0.f, 0.f, 0.f, 0.f);
    int e = beg;
    for (; e + 4 <= end; e += 4) {
        int s0 = g_esrc[e],     s1 = g_esrc[e + 1];
        int s2 = g_esrc[e + 2], s3 = g_esrc[e + 3];
        float w0 = g_norm_out[s0], w1 = g_norm_out[s1];
        float w2 = g_norm_out[s2], w3 = g_norm_out[s3];
        float4 v0 = base[(size_t)s0 * SF4 + t];
        float4 v1 = base[(size_t)s1 * SF4 + t];
        float4 v2 = base[(size_t)s2 * SF4 + t];
        float4 v3 = base[(size_t)s3 * SF4 + t];
        a.x += v0.x * w0 + v1.x * w1;  b.x += v2.x * w2 + v3.x * w3;
        a.y += v0.y * w0 + v1.y * w1;  b.y += v2.y * w2 + v3.y * w3;
        a.z += v0.z * w0 + v1.z * w1;  b.z += v2.z * w2 + v3.z * w3;
        a.w += v0.w * w0 + v1.w * w1;  b.w += v2.w * w2 + v3.w * w3;
    }
    for (; e < end; e++) {
        int s = g_esrc[e];
        float w = g_norm_out[s];
        float4 v = base[(size_t)s * SF4 + t];
        a.x += v.x * w; a.y += v.y * w; a.z += v.z * w; a.w += v.w * w;
    }
    float ni = g_norm_in[n];
    __half2 h0 = __floats2half2_rn((a.x + b.x) * ni, (a.y + b.y) * ni);
    __half2 h1 = __floats2half2_rn((a.z + b.z) * ni, (a.w + b.w) * ni);
    uint2 u;
    u.x = *reinterpret_cast<uint32_t*>(&h0);
    u.y = *reinterpret_cast<uint32_t*>(&h1);
    int m   = n * 2 + (t >> 5);         // GEMM row
    int col = (t & 31) * 4;
    *reinterpret_cast<uint2*>(&g_abuf0[(size_t)m * IN_F + col]) = u;
}

// ---------------- layers 1/2 aggregation: fp16 gather -> fp32 acc -> fp16 ----
__global__ void k_aggh() {
    int n = blockIdx.x;
    int t = threadIdx.x;           // 0..63
    if (t >= NODE_U4) return;      // 62 active lanes
    int beg = g_rowptr[n];
    int end = g_rowptr[n + 1];
    const uint4* base = reinterpret_cast<const uint4*>(g_hbuf);
    float a[8], b[8];
    #pragma unroll
    for (int q = 0; q < 8; q++) { a[q] = 0.f; b[q] = 0.f; }

    auto addu4 = [](float* acc, uint4 u) {
        const __half2* h2 = reinterpret_cast<const __half2*>(&u);
        #pragma unroll
        for (int q = 0; q < 4; q++) {
            float2 f = __half22float2(h2[q]);
            acc[2 * q]     += f.x;
            acc[2 * q + 1] += f.y;
        }
    };

    int e = beg;
    for (; e + 4 <= end; e += 4) {
        int s0 = g_esrc[e],     s1 = g_esrc[e + 1];
        int s2 = g_esrc[e + 2], s3 = g_esrc[e + 3];
        uint4 u0 = base[(size_t)s0 * NODE_U4 + t];
        uint4 u1 = base[(size_t)s1 * NODE_U4 + t];
        uint4 u2 = base[(size_t)s2 * NODE_U4 + t];
        uint4 u3 = base[(size_t)s3 * NODE_U4 + t];
        addu4(a, u0); addu4(b, u1); addu4(a, u2); addu4(b, u3);
    }
    for (; e < end; e++) {
        uint4 u = base[(size_t)g_esrc[e] * NODE_U4 + t];
        addu4(a, u);
    }
    float ni = g_norm_in[n];
    __half2 h[4];
    #pragma unroll
    for (int q = 0; q < 4; q++)
        h[q] = __floats2half2_rn((a[2 * q] + b[2 * q]) * ni,
                                 (a[2 * q + 1] + b[2 * q + 1]) * ni);
    uint4 o;
    o.x = *reinterpret_cast<uint32_t*>(&h[0]);
    o.y = *reinterpret_cast<uint32_t*>(&h[1]);
    o.z = *reinterpret_cast<uint32_t*>(&h[2]);
    o.w = *reinterpret_cast<uint32_t*>(&h[3]);
    reinterpret_cast<uint4*>(g_abuf)[(size_t)n * NODE_U4 + t] = o;
}

// ---------------- fp16 tensor-core GEMM (double-buffered, reg-prefetched) ----
// C(fp16) = relu(A[M,K,lda] @ W[K,246] + b) * (use_scale ? norm_out : 1)
#define MMA_F16(c, a, b)                                               \
    asm volatile(                                                      \
        "mma.sync.aligned.m16n8k16.row.col.f32.f16.f16.f32 "           \
        "{%0,%1,%2,%3}, {%4,%5,%6,%7}, {%8,%9}, {%0,%1,%2,%3};"        \
        : "+f"((c)[0]), "+f"((c)[1]), "+f"((c)[2]), "+f"((c)[3])       \
        : "r"((a)[0]), "r"((a)[1]), "r"((a)[2]), "r"((a)[3]),          \
          "r"((b)[0]), "r"((b)[1]))

constexpr int BM = 128, BN = 128, BK = 16;

__global__ void __launch_bounds__(256)
k_gemm(int ktiles, int lda, int which_a, int wsel,
       const float* __restrict__ bias, int use_scale) {
    __shared__ uint32_t As[2][BK / 2][BM + 8];   // [buf][kpair][m], half2 elems
    __shared__ uint32_t Bs[2][BK / 2][BN + 8];   // [buf][kpair][n]

    const __half*   A  = which_a ? g_abuf : g_abuf0;
    const uint32_t* Wp = g_wp[wsel];

    int tid = threadIdx.x;
    int lane = tid & 31, warp = tid >> 5;
    int wm = (warp & 1) * 64;     // 2 warps along M
    int wn = (warp >> 1) * 32;    // 4 warps along N
    int row0 = blockIdx.y * BM;
    int col0 = blockIdx.x * BN;

    // A loads: thread covers 4 halves (2 kpairs) x 2 rows
    int a_k4 = (tid & 3) * 4;     // half offset within tile: 0,4,8,12
    int a_rb = tid >> 2;          // 0..63
    // B loads: thread covers 4 cols x 1 kpair
    int b_kp = tid >> 5;          // 0..7
    int b_c  = (tid & 31) * 4;    // 0..124

    uint2 aR[2];
    uint4 bR;

    auto load_tile = [&](int kt) {
        int k0 = kt * BK;
        #pragma unroll
        for (int it = 0; it < 2; it++) {
            int grow = row0 + a_rb + it * 64;
            int koff = k0 + a_k4;
            aR[it] = make_uint2(0u, 0u);
            if (grow < MROWS && koff + 4 <= lda)
                aR[it] = *reinterpret_cast<const uint2*>(&A[(size_t)grow * lda + koff]);
        }
        bR = *reinterpret_cast<const uint4*>(
            &Wp[(size_t)(k0 / 2 + b_kp) * WPN + col0 + b_c]);
    };
    auto store_tile = [&](int buf) {
        int kp = (tid & 3) * 2;
        #pragma unroll
        for (int it = 0; it < 2; it++) {
            As[buf][kp][a_rb + it * 64]     = aR[it].x;
            As[buf][kp + 1][a_rb + it * 64] = aR[it].y;
        }
        *reinterpret_cast<uint4*>(&Bs[buf][b_kp][b_c]) = bR;
    };

    float c[4][4][4];
    #pragma unroll
    for (int mi = 0; mi < 4; mi++)
        #pragma unroll
        for (int nj = 0; nj < 4; nj++)
            #pragma unroll
            for (int q = 0; q < 4; q++) c[mi][nj][q] = 0.f;

    load_tile(0);
    store_tile(0);
    __syncthreads();

    for (int kt = 0; kt < ktiles; kt++) {
        int cur = kt & 1;
        bool more = (kt + 1) < ktiles;
        if (more) load_tile(kt + 1);          // LDGs fly during MMA below

        uint32_t a[4][4], b[4][2];
        int kq = lane & 3;                    // kpair low index 0..3
        int mb = wm + (lane >> 2);
        #pragma unroll
        for (int mi = 0; mi < 4; mi++) {
            a[mi][0] = As[cur][kq][mb + mi * 16];
            a[mi][1] = As[cur][kq][mb + mi * 16 + 8];
            a[mi][2] = As[cur][kq + 4][mb + mi * 16];
            a[mi][3] = As[cur][kq + 4][mb + mi * 16 + 8];
        }
        int nb = wn + (lane >> 2);
        #pragma unroll
        for (int nj = 0; nj < 4; nj++) {
            b[nj][0] = Bs[cur][kq][nb + nj * 8];
            b[nj][1] = Bs[cur][kq + 4][nb + nj * 8];
        }
        #pragma unroll
        for (int mi = 0; mi < 4; mi++)
            #pragma unroll
            for (int nj = 0; nj < 4; nj++)
                MMA_F16(c[mi][nj], a[mi], b[nj]);

        if (more) {
            store_tile(cur ^ 1);
            __syncthreads();
        }
    }

    // epilogue: bias + relu (+ optional norm_out pre-scale), fp16 half2 stores
    #pragma unroll
    for (int mi = 0; mi < 4; mi++) {
        int r  = row0 + wm + mi * 16 + (lane >> 2);
        int r2 = r + 8;
        float sc  = 1.f, sc2 = 1.f;
        if (use_scale) {
            if (r  < MROWS) sc  = g_norm_out[r >> 1];
            if (r2 < MROWS) sc2 = g_norm_out[r2 >> 1];
        }
        #pragma unroll
        for (int nj = 0; nj < 4; nj++) {
            int cc = col0 + wn + nj * 8 + (lane & 3) * 2;
            if (cc >= H) continue;           // H even -> pair never straddles
            float b0 = bias[cc];
            float b1 = bias[cc + 1];
            if (r < MROWS) {
                float v0 = fmaxf(c[mi][nj][0] + b0, 0.f) * sc;
                float v1 = fmaxf(c[mi][nj][1] + b1, 0.f) * sc;
                *reinterpret_cast<__half2*>(&g_hbuf[(size_t)r * HP + cc]) =
                    __floats2half2_rn(v0, v1);
            }
            if (r2 < MROWS) {
                float v2 = fmaxf(c[mi][nj][2] + b0, 0.f) * sc2;
                float v3 = fmaxf(c[mi][nj][3] + b1, 0.f) * sc2;
                *reinterpret_cast<__half2*>(&g_hbuf[(size_t)r2 * HP + cc]) =
                    __floats2half2_rn(v2, v3);
            }
        }
    }
}

// ---------------- final fc: out[n] = fc_b + mean_s(h[n,s,:]) @ fc_w ----------
__global__ void k_fc(const float* __restrict__ fcw, const float* __restrict__ fcb,
                     float* __restrict__ out) {
    int gwarp = (blockIdx.x * blockDim.x + threadIdx.x) >> 5;
    int lane = threadIdx.x & 31;
    if (gwarp >= NN) return;
    const __half2* p = reinterpret_cast<const __half2*>(g_hbuf + (size_t)gwarp * (S * HP));
    float acc = 0.f;
    for (int q = lane; q < S * HP / 2; q += 32) {   // 248 half2 per node
        int row = (q >= HP / 2) ? 1 : 0;
        int col = (q - row * (HP / 2)) * 2;
        if (col >= H) continue;                      // pad columns
        float2 f = __half22float2(p[q]);
        acc += f.x * fcw[col] + f.y * fcw[col + 1];
    }
    #pragma unroll
    for (int off = 16; off; off >>= 1)
        acc += __shfl_down_sync(0xffffffffu, acc, off);
    if (lane == 0) out[gwarp] = fcb[0] + acc * (1.0f / S);
}

// ---------------- launch -----------------------------------------------------
extern "C" void kernel_launch(void* const* d_in, const int* in_sizes, int n_in,
                              void* d_out, int out_size) {
    const float* feat = (const float*)d_in[0];
    const int*   src  = (const int*)d_in[1];
    const int*   dst  = (const int*)d_in[2];
    const float* W0   = (const float*)d_in[3];
    const float* b0   = (const float*)d_in[4];
    const float* W1   = (const float*)d_in[5];
    const float* b1   = (const float*)d_in[6];
    const float* W2   = (const float*)d_in[7];
    const float* b2   = (const float*)d_in[8];
    const float* fcw  = (const float*)d_in[9];
    const float* fcb  = (const float*)d_in[10];
    float* out = (float*)d_out;

    // zero degree arrays via async memset (graph-capturable)
    void* p_out; void* p_in;
    cudaGetSymbolAddress(&p_out, g_outdeg);
    cudaGetSymbolAddress(&p_in,  g_indeg);
    cudaMemsetAsync(p_out, 0, NN * sizeof(int), 0);
    cudaMemsetAsync(p_in,  0, NN * sizeof(int), 0);

    // weight pre-pack (independent of graph build)
    k_convw<<<dim3(128, 3), 256>>>(W0, W1, W2);

    // graph build: deg (+scanstate reset) -> one-kernel scan -> scatter
    k_deg<<<(EE + 255) / 256, 256>>>(src, dst);
    k_scan1<<<NBLK, 256>>>();
    k_scatter<<<(EE + 255) / 256, 256>>>(src, dst);

    dim3 gg(2, (MROWS + BM - 1) / BM);

    // layer 0: fused prescale+aggregate (fp16 out) -> fp16 GEMM K=128
    k_agg0<<<NN, S * IN_F / 4>>>(feat);
    k_gemm<<<gg, 256>>>(IN_F / BK, IN_F, /*which_a=*/0, /*wsel=*/0, b0, /*use_scale=*/1);

    // layer 1: fp16 gather-agg -> fp16 GEMM K=246 (16 k-tiles), lda=248
    k_aggh<<<NN, 64>>>();
    k_gemm<<<gg, 256>>>((H + BK - 1) / BK, HP, 1, 1, b1, /*use_scale=*/1);

    // layer 2 (no pre-scale; feeds fc)
    k_aggh<<<NN, 64>>>();
    k_gemm<<<gg, 256>>>((H + BK - 1) / BK, HP, 1, 2, b2, /*use_scale=*/0);

    // readout
    k_fc<<<(NN * 32 + 255) / 256, 256>>>(fcw, fcb, out);
}

// round 17
// speedup vs baseline: 1.2945x; 1.0082x over previous
#include <cuda_runtime.h>
#include <cuda_fp16.h>
#include <cstdint>

// Problem constants (fixed by the dataset)
constexpr int NN   = 20000;     // nodes
constexpr int EE   = 320000;    // edges
constexpr int S    = 2;         // feature axis
constexpr int IN_F = 128;       // in features
constexpr int H    = 246;       // hidden
constexpr int HP   = 248;       // padded hidden
constexpr int MROWS = NN * S;   // 40000 GEMM rows
constexpr int NBLK = (NN + 255) / 256;  // 79
constexpr int NU4_0 = (S * IN_F) / 8;   // 32 uint4 lanes per node (layer 0)
constexpr int NU4_H = (S * HP) / 8;     // 62 uint4 lanes per node (layers 1/2)
constexpr int WPN = 256;        // padded W columns (half2 units)

// ---------------- static device scratch (no allocations allowed) -------------
// zero-initialized at module load; pad regions are never written -> stay 0
__device__ __align__(128) __half   g_fh   [MROWS * IN_F]; // fp16 norm_out*feat
__device__ __align__(128) __half   g_abuf0[MROWS * IN_F]; // layer-0 agg out
__device__ __align__(128) __half   g_abuf [MROWS * HP];   // layer-1/2 agg out
__device__ __align__(128) __half   g_hbuf [MROWS * HP];   // GEMM out (fp16)
__device__ __align__(128) uint32_t g_wp[3][128 * WPN];    // k-pair-packed weights
__device__ float g_norm_out[NN];
__device__ float g_norm_in[NN];
__device__ int   g_outdeg[NN];
__device__ int   g_indeg[NN];
__device__ int   g_rowptr[NN + 1];
__device__ int   g_cursor[NN];
__device__ int   g_esrc[EE];
__device__ unsigned long long g_scanstate[NBLK];

// ---------------- weight pre-conversion: fp32 [K][246] -> half2 [kp][256] ----
__global__ void k_convw(const float* __restrict__ W0, const float* __restrict__ W1,
                        const float* __restrict__ W2) {
    int w = blockIdx.y, kp = blockIdx.x, c = threadIdx.x;
    const float* W = (w == 0) ? W0 : (w == 1) ? W1 : W2;
    int K = (w == 0) ? IN_F : H;
    if (c >= H || 2 * kp + 1 >= K) return;
    __half2 h = __floats2half2_rn(W[(size_t)(2 * kp) * H + c],
                                  W[(size_t)(2 * kp + 1) * H + c]);
    g_wp[w][kp * WPN + c] = *reinterpret_cast<uint32_t*>(&h);
}

// ---------------- feature conversion: fp32 feat * norm_out -> fp16 -----------
// one uint4 (8 halves) per thread; 32 uint4 per node
__global__ void k_convf(const float* __restrict__ feat) {
    int idx = blockIdx.x * blockDim.x + threadIdx.x;
    if (idx >= MROWS * IN_F / 8) return;
    int node = idx >> 5;                  // 32 uint4 per node
    float w = g_norm_out[node];
    const float4* f4 = reinterpret_cast<const float4*>(feat) + (size_t)idx * 2;
    float4 x = f4[0], y = f4[1];
    __half2 h0 = __floats2half2_rn(x.x * w, x.y * w);
    __half2 h1 = __floats2half2_rn(x.z * w, x.w * w);
    __half2 h2 = __floats2half2_rn(y.x * w, y.y * w);
    __half2 h3 = __floats2half2_rn(y.z * w, y.w * w);
    uint4 o;
    o.x = *reinterpret_cast<uint32_t*>(&h0);
    o.y = *reinterpret_cast<uint32_t*>(&h1);
    o.z = *reinterpret_cast<uint32_t*>(&h2);
    o.w = *reinterpret_cast<uint32_t*>(&h3);
    reinterpret_cast<uint4*>(g_fh)[idx] = o;
}

// ---------------- graph preprocessing ---------------------------------------
__global__ void k_deg(const int* __restrict__ src, const int* __restrict__ dst) {
    int i = blockIdx.x * blockDim.x + threadIdx.x;
    if (i < NBLK) g_scanstate[i] = 0ull;   // reset lookback state for k_scan1
    if (i < EE) {
        atomicAdd(&g_outdeg[src[i]], 1);
        atomicAdd(&g_indeg[dst[i]], 1);
    }
}

// single-kernel scan: local scan + warp-parallel lookback over block aggregates
__global__ void k_scan1() {   // NBLK blocks x 256
    __shared__ int sd[256];
    __shared__ int s_base;
    int t = threadIdx.x, b = blockIdx.x;
    int i = b * 256 + t;
    int deg = (i < NN) ? g_indeg[i] : 0;
    int v = deg;
    sd[t] = v; __syncthreads();
    #pragma unroll
    for (int off = 1; off < 256; off <<= 1) {
        int tmp = (t >= off) ? sd[t - off] : 0;
        __syncthreads();
        v += tmp; sd[t] = v;
        __syncthreads();
    }
    int total = sd[255];
    if (t == 0)
        atomicExch(&g_scanstate[b], (1ull << 32) | (unsigned)total);
    if (t < 32) {
        long long acc = 0;
        for (int j = b - 1 - t; j >= 0; j -= 32) {
            unsigned long long s;
            do { s = atomicAdd(&g_scanstate[j], 0ull); } while ((s >> 32) == 0);
            acc += (int)(s & 0xffffffffull);
        }
        #pragma unroll
        for (int off = 16; off; off >>= 1)
            acc += __shfl_down_sync(0xffffffffu, acc, off);
        if (t == 0) s_base = (int)acc;
    }
    __syncthreads();
    int base = s_base;
    if (i < NN) {
        g_rowptr[i + 1] = base + v;
        g_cursor[i]     = base + v - deg;
        g_norm_in[i]    = rsqrtf((float)max(deg, 1));
        g_norm_out[i]   = rsqrtf((float)max(g_outdeg[i], 1));
    }
    if (i == 0) g_rowptr[0] = 0;
}

__global__ void k_scatter(const int* __restrict__ src, const int* __restrict__ dst) {
    int i = blockIdx.x * blockDim.x + threadIdx.x;
    if (i < EE) {
        int p = atomicAdd(&g_cursor[dst[i]], 1);
        g_esrc[p] = src[i];
    }
}

// ---------------- unified fp16 aggregation ----------------------------------
// out[n] = norm_in[n] * sum_{s in N(n)} in[s]; rows are NU4 uint4 wide.
// 8-edge unroll for MLP; fp16 pairwise pre-add (1 extra rounding per pair)
// then fp32 accumulate.
template <int NU4>
__global__ void k_agg_f16(const __half* __restrict__ in, __half* __restrict__ out) {
    int n = blockIdx.x;
    int t = threadIdx.x;
    if (t >= NU4) return;
    int beg = g_rowptr[n];
    int end = g_rowptr[n + 1];
    const uint4* base = reinterpret_cast<const uint4*>(in);

    float a[8], b[8];
    #pragma unroll
    for (int q = 0; q < 8; q++) { a[q] = 0.f; b[q] = 0.f; }

    auto addpair = [](float* acc, uint4 u, uint4 v) {
        const __half2* hu = reinterpret_cast<const __half2*>(&u);
        const __half2* hv = reinterpret_cast<const __half2*>(&v);
        #pragma unroll
        for (int q = 0; q < 4; q++) {
            float2 f = __half22float2(__hadd2(hu[q], hv[q]));
            acc[2 * q]     += f.x;
            acc[2 * q + 1] += f.y;
        }
    };
    auto addone = [](float* acc, uint4 u) {
        const __half2* hu = reinterpret_cast<const __half2*>(&u);
        #pragma unroll
        for (int q = 0; q < 4; q++) {
            float2 f = __half22float2(hu[q]);
            acc[2 * q]     += f.x;
            acc[2 * q + 1] += f.y;
        }
    };

    int e = beg;
    for (; e + 8 <= end; e += 8) {
        int s0 = g_esrc[e],     s1 = g_esrc[e + 1];
        int s2 = g_esrc[e + 2], s3 = g_esrc[e + 3];
        int s4 = g_esrc[e + 4], s5 = g_esrc[e + 5];
        int s6 = g_esrc[e + 6], s7 = g_esrc[e + 7];
        uint4 u0 = base[(size_t)s0 * NU4 + t];
        uint4 u1 = base[(size_t)s1 * NU4 + t];
        uint4 u2 = base[(size_t)s2 * NU4 + t];
        uint4 u3 = base[(size_t)s3 * NU4 + t];
        uint4 u4 = base[(size_t)s4 * NU4 + t];
        uint4 u5 = base[(size_t)s5 * NU4 + t];
        uint4 u6 = base[(size_t)s6 * NU4 + t];
        uint4 u7 = base[(size_t)s7 * NU4 + t];
        addpair(a, u0, u1); addpair(b, u2, u3);
        addpair(a, u4, u5); addpair(b, u6, u7);
    }
    for (; e + 2 <= end; e += 2) {
        int s0 = g_esrc[e], s1 = g_esrc[e + 1];
        uint4 u0 = base[(size_t)s0 * NU4 + t];
        uint4 u1 = base[(size_t)s1 * NU4 + t];
        addpair(a, u0, u1);
    }
    if (e < end)
        addone(a, base[(size_t)g_esrc[e] * NU4 + t]);

    float ni = g_norm_in[n];
    __half2 h[4];
    #pragma unroll
    for (int q = 0; q < 4; q++)
        h[q] = __floats2half2_rn((a[2 * q] + b[2 * q]) * ni,
                                 (a[2 * q + 1] + b[2 * q + 1]) * ni);
    uint4 o;
    o.x = *reinterpret_cast<uint32_t*>(&h[0]);
    o.y = *reinterpret_cast<uint32_t*>(&h[1]);
    o.z = *reinterpret_cast<uint32_t*>(&h[2]);
    o.w = *reinterpret_cast<uint32_t*>(&h[3]);
    reinterpret_cast<uint4*>(out)[(size_t)n * NU4 + t] = o;
}

// ---------------- fp16 tensor-core GEMM (double-buffered, reg-prefetched) ----
// C(fp16) = relu(A[M,K,lda] @ W[K,246] + b) * (use_scale ? norm_out : 1)
#define MMA_F16(c, a, b)                                               \
    asm volatile(                                                      \
        "mma.sync.aligned.m16n8k16.row.col.f32.f16.f16.f32 "           \
        "{%0,%1,%2,%3}, {%4,%5,%6,%7}, {%8,%9}, {%0,%1,%2,%3};"        \
        : "+f"((c)[0]), "+f"((c)[1]), "+f"((c)[2]), "+f"((c)[3])       \
        : "r"((a)[0]), "r"((a)[1]), "r"((a)[2]), "r"((a)[3]),          \
          "r"((b)[0]), "r"((b)[1]))

constexpr int BM = 128, BN = 128, BK = 16;

__global__ void __launch_bounds__(256)
k_gemm(int ktiles, int lda, int which_a, int wsel,
       const float* __restrict__ bias, int use_scale) {
    __shared__ uint32_t As[2][BK / 2][BM + 8];   // [buf][kpair][m], half2 elems
    __shared__ uint32_t Bs[2][BK / 2][BN + 8];   // [buf][kpair][n]

    const __half*   A  = which_a ? g_abuf : g_abuf0;
    const uint32_t* Wp = g_wp[wsel];

    int tid = threadIdx.x;
    int lane = tid & 31, warp = tid >> 5;
    int wm = (warp & 1) * 64;     // 2 warps along M
    int wn = (warp >> 1) * 32;    // 4 warps along N
    int row0 = blockIdx.y * BM;
    int col0 = blockIdx.x * BN;

    int a_k4 = (tid & 3) * 4;     // half offset within tile: 0,4,8,12
    int a_rb = tid >> 2;          // 0..63
    int b_kp = tid >> 5;          // 0..7
    int b_c  = (tid & 31) * 4;    // 0..124

    uint2 aR[2];
    uint4 bR;

    auto load_tile = [&](int kt) {
        int k0 = kt * BK;
        #pragma unroll
        for (int it = 0; it < 2; it++) {
            int grow = row0 + a_rb + it * 64;
            int koff = k0 + a_k4;
            aR[it] = make_uint2(0u, 0u);
            if (grow < MROWS && koff + 4 <= lda)
                aR[it] = *reinterpret_cast<const uint2*>(&A[(size_t)grow * lda + koff]);
        }
        bR = *reinterpret_cast<const uint4*>(
            &Wp[(size_t)(k0 / 2 + b_kp) * WPN + col0 + b_c]);
    };
    auto store_tile = [&](int buf) {
        int kp = (tid & 3) * 2;
        #pragma unroll
        for (int it = 0; it < 2; it++) {
            As[buf][kp][a_rb + it * 64]     = aR[it].x;
            As[buf][kp + 1][a_rb + it * 64] = aR[it].y;
        }
        *reinterpret_cast<uint4*>(&Bs[buf][b_kp][b_c]) = bR;
    };

    float c[4][4][4];
    #pragma unroll
    for (int mi = 0; mi < 4; mi++)
        #pragma unroll
        for (int nj = 0; nj < 4; nj++)
            #pragma unroll
            for (int q = 0; q < 4; q++) c[mi][nj][q] = 0.f;

    load_tile(0);
    store_tile(0);
    __syncthreads();

    for (int kt = 0; kt < ktiles; kt++) {
        int cur = kt & 1;
        bool more = (kt + 1) < ktiles;
        if (more) load_tile(kt + 1);          // LDGs fly during MMA below

        uint32_t a[4][4], b[4][2];
        int kq = lane & 3;
        int mb = wm + (lane >> 2);
        #pragma unroll
        for (int mi = 0; mi < 4; mi++) {
            a[mi][0] = As[cur][kq][mb + mi * 16];
            a[mi][1] = As[cur][kq][mb + mi * 16 + 8];
            a[mi][2] = As[cur][kq + 4][mb + mi * 16];
            a[mi][3] = As[cur][kq + 4][mb + mi * 16 + 8];
        }
        int nb = wn + (lane >> 2);
        #pragma unroll
        for (int nj = 0; nj < 4; nj++) {
            b[nj][0] = Bs[cur][kq][nb + nj * 8];
            b[nj][1] = Bs[cur][kq + 4][nb + nj * 8];
        }
        #pragma unroll
        for (int mi = 0; mi < 4; mi++)
            #pragma unroll
            for (int nj = 0; nj < 4; nj++)
                MMA_F16(c[mi][nj], a[mi], b[nj]);

        if (more) {
            store_tile(cur ^ 1);
            __syncthreads();
        }
    }

    // epilogue: bias + relu (+ optional norm_out pre-scale), fp16 half2 stores
    #pragma unroll
    for (int mi = 0; mi < 4; mi++) {
        int r  = row0 + wm + mi * 16 + (lane >> 2);
        int r2 = r + 8;
        float sc  = 1.f, sc2 = 1.f;
        if (use_scale) {
            if (r  < MROWS) sc  = g_norm_out[r >> 1];
            if (r2 < MROWS) sc2 = g_norm_out[r2 >> 1];
        }
        #pragma unroll
        for (int nj = 0; nj < 4; nj++) {
            int cc = col0 + wn + nj * 8 + (lane & 3) * 2;
            if (cc >= H) continue;           // H even -> pair never straddles
            float b0 = bias[cc];
            float b1 = bias[cc + 1];
            if (r < MROWS) {
                float v0 = fmaxf(c[mi][nj][0] + b0, 0.f) * sc;
                float v1 = fmaxf(c[mi][nj][1] + b1, 0.f) * sc;
                *reinterpret_cast<__half2*>(&g_hbuf[(size_t)r * HP + cc]) =
                    __floats2half2_rn(v0, v1);
            }
            if (r2 < MROWS) {
                float v2 = fmaxf(c[mi][nj][2] + b0, 0.f) * sc2;
                float v3 = fmaxf(c[mi][nj][3] + b1, 0.f) * sc2;
                *reinterpret_cast<__half2*>(&g_hbuf[(size_t)r2 * HP + cc]) =
                    __floats2half2_rn(v2, v3);
            }
        }
    }
}

// ---------------- final fc: out[n] = fc_b + mean_s(h[n,s,:]) @ fc_w ----------
__global__ void k_fc(const float* __restrict__ fcw, const float* __restrict__ fcb,
                     float* __restrict__ out) {
    int gwarp = (blockIdx.x * blockDim.x + threadIdx.x) >> 5;
    int lane = threadIdx.x & 31;
    if (gwarp >= NN) return;
    const __half2* p = reinterpret_cast<const __half2*>(g_hbuf + (size_t)gwarp * (S * HP));
    float acc = 0.f;
    for (int q = lane; q < S * HP / 2; q += 32) {   // 248 half2 per node
        int row = (q >= HP / 2) ? 1 : 0;
        int col = (q - row * (HP / 2)) * 2;
        if (col >= H) continue;                      // pad columns
        float2 f = __half22float2(p[q]);
        acc += f.x * fcw[col] + f.y * fcw[col + 1];
    }
    #pragma unroll
    for (int off = 16; off; off >>= 1)
        acc += __shfl_down_sync(0xffffffffu, acc, off);
    if (lane == 0) out[gwarp] = fcb[0] + acc * (1.0f / S);
}

// ---------------- launch -----------------------------------------------------
extern "C" void kernel_launch(void* const* d_in, const int* in_sizes, int n_in,
                              void* d_out, int out_size) {
    const float* feat = (const float*)d_in[0];
    const int*   src  = (const int*)d_in[1];
    const int*   dst  = (const int*)d_in[2];
    const float* W0   = (const float*)d_in[3];
    const float* b0   = (const float*)d_in[4];
    const float* W1   = (const float*)d_in[5];
    const float* b1   = (const float*)d_in[6];
    const float* W2   = (const float*)d_in[7];
    const float* b2   = (const float*)d_in[8];
    const float* fcw  = (const float*)d_in[9];
    const float* fcb  = (const float*)d_in[10];
    float* out = (float*)d_out;

    // zero degree arrays via async memset (graph-capturable)
    void* p_out; void* p_in;
    cudaGetSymbolAddress(&p_out, g_outdeg);
    cudaGetSymbolAddress(&p_in,  g_indeg);
    cudaMemsetAsync(p_out, 0, NN * sizeof(int), 0);
    cudaMemsetAsync(p_in,  0, NN * sizeof(int), 0);

    // weight pre-pack (independent of graph build)
    k_convw<<<dim3(128, 3), 256>>>(W0, W1, W2);

    // graph build: deg (+scanstate reset) -> one-kernel scan -> scatter
    k_deg<<<(EE + 255) / 256, 256>>>(src, dst);
    k_scan1<<<NBLK, 256>>>();
    // feature conversion needs norm_out (from k_scan1); scatter is independent
    k_convf<<<(MROWS * IN_F / 8 + 255) / 256, 256>>>(feat);
    k_scatter<<<(EE + 255) / 256, 256>>>(src, dst);

    __half* fh;  cudaGetSymbolAddress((void**)&fh,  g_fh);
    __half* ab0; cudaGetSymbolAddress((void**)&ab0, g_abuf0);
    __half* ab;  cudaGetSymbolAddress((void**)&ab,  g_abuf);
    __half* hb;  cudaGetSymbolAddress((void**)&hb,  g_hbuf);

    dim3 gg(2, (MROWS + BM - 1) / BM);

    // layer 0: fp16 gather-agg over converted features -> fp16 GEMM K=128
    k_agg_f16<NU4_0><<<NN, 32>>>(fh, ab0);
    k_gemm<<<gg, 256>>>(IN_F / BK, IN_F, /*which_a=*/0, /*wsel=*/0, b0, /*use_scale=*/1);

    // layer 1: fp16 gather-agg -> fp16 GEMM K=246 (16 k-tiles), lda=248
    k_agg_f16<NU4_H><<<NN, 64>>>(hb, ab);
    k_gemm<<<gg, 256>>>((H + BK - 1) / BK, HP, 1, 1, b1, /*use_scale=*/1);

    // layer 2 (no pre-scale; feeds fc)
    k_agg_f16<NU4_H><<<NN, 64>>>(hb, ab);
    k_gemm<<<gg, 256>>>((H + BK - 1) / BK, HP, 1, 2, b2, /*use_scale=*/0);

    // readout
    k_fc<<<(NN * 32 + 255) / 256, 256>>>(fcw, fcb, out);
}